// round 9
// baseline (speedup 1.0000x reference)
#include <cuda_runtime.h>
#include <cuda_bf16.h>
#include <mma.h>
#include <math.h>
#include <stdint.h>

using namespace nvcuda;

// Problem constants
#define BATCH 4
#define SEQ   2048
#define EMB   1024
#define HEADS 16
#define HD    64
#define MROWS (BATCH * SEQ)          // 8192
#define QKVN  (3 * EMB)              // 3072

// ---------------------------------------------------------------------------
// Device-global scratch (no allocation allowed)
// ---------------------------------------------------------------------------
__device__ float g_q[BATCH * HEADS * SEQ * HD];   // [B,H,S,hd] fp32
__device__ float g_k[BATCH * HEADS * SEQ * HD];
__device__ float g_v[BATCH * HEADS * SEQ * HD];

// bf16 split-precision operand buffers
__device__ __nv_bfloat16 g_ah[MROWS * EMB], g_al[MROWS * EMB];   // hidden
__device__ __nv_bfloat16 g_wh[QKVN * EMB],  g_wl[QKVN * EMB];    // qkv_w
__device__ __nv_bfloat16 g_ph[EMB * EMB],   g_pl[EMB * EMB];     // proj_w
__device__ __nv_bfloat16 g_aoh[MROWS * EMB], g_aol[MROWS * EMB]; // attn out

// ---------------------------------------------------------------------------
// small helpers
// ---------------------------------------------------------------------------
__device__ __forceinline__ uint32_t smem_u32(const void* p) {
    uint32_t a;
    asm("{ .reg .u64 t; cvta.to.shared.u64 t, %1; cvt.u32.u64 %0, t; }"
        : "=r"(a) : "l"(p));
    return a;
}
__device__ __forceinline__ void cp_async16(uint32_t dst, const void* src) {
    asm volatile("cp.async.cg.shared.global [%0], [%1], 16;"
                 :: "r"(dst), "l"(src) : "memory");
}
__device__ __forceinline__ void cp_commit() {
    asm volatile("cp.async.commit_group;" ::: "memory");
}
template <int N>
__device__ __forceinline__ void cp_wait() {
    asm volatile("cp.async.wait_group %0;" :: "n"(N) : "memory");
}

// ---------------------------------------------------------------------------
// fp32 -> (bf16 hi, bf16 lo) split conversion.  WHICH: 0=hidden 1=qkv_w 2=proj_w
// ---------------------------------------------------------------------------
template <int WHICH>
__global__ __launch_bounds__(256)
void split_kernel(const float* __restrict__ x, int n4)
{
    __nv_bfloat16* hi = (WHICH == 0) ? g_ah : (WHICH == 1) ? g_wh : g_ph;
    __nv_bfloat16* lo = (WHICH == 0) ? g_al : (WHICH == 1) ? g_wl : g_pl;
    int i = blockIdx.x * 256 + threadIdx.x;
    if (i >= n4) return;
    float4 v = reinterpret_cast<const float4*>(x)[i];
    __nv_bfloat16 h0 = __float2bfloat16_rn(v.x);
    __nv_bfloat16 h1 = __float2bfloat16_rn(v.y);
    __nv_bfloat16 h2 = __float2bfloat16_rn(v.z);
    __nv_bfloat16 h3 = __float2bfloat16_rn(v.w);
    __nv_bfloat16 l0 = __float2bfloat16_rn(v.x - __bfloat162float(h0));
    __nv_bfloat16 l1 = __float2bfloat16_rn(v.y - __bfloat162float(h1));
    __nv_bfloat16 l2 = __float2bfloat16_rn(v.z - __bfloat162float(h2));
    __nv_bfloat16 l3 = __float2bfloat16_rn(v.w - __bfloat162float(h3));
    __nv_bfloat162* hp = reinterpret_cast<__nv_bfloat162*>(hi) + 2 * i;
    __nv_bfloat162* lp = reinterpret_cast<__nv_bfloat162*>(lo) + 2 * i;
    hp[0] = __halves2bfloat162(h0, h1);
    hp[1] = __halves2bfloat162(h2, h3);
    lp[0] = __halves2bfloat162(l0, l1);
    lp[1] = __halves2bfloat162(l2, l3);
}

// ---------------------------------------------------------------------------
// WMMA split-bf16 GEMM:  C[m,n] = sum_k A[m,k]*W[n,k] + bias[n]
// via Ah*Wh + Ah*Wl + Al*Wh with fp32 accumulators (HMMA mma.sync path).
// CTA tile 128x128, BK=32, 8 warps each 32(M)x64(N), cp.async double buffer.
// MODE 1: A=g_ah/g_al, W=g_wh/g_wl, epilogue scatters into g_q/g_k/g_v.
// MODE 2: A=g_aoh/g_aol, W=g_ph/g_pl, epilogue writes C (+bias).
// ---------------------------------------------------------------------------
#define BK      32
#define LDS_AB  40                        // padded row length (elems)
#define TILE_EL (128 * LDS_AB)            // elems per tile buffer
#define TILE_B  (TILE_EL * 2)             // bytes per tile (10240)
#define BUF_B   (4 * TILE_B)              // Ah, Al, Bh, Bl (40960)
#define GSMEM   (2 * BUF_B)               // 81920 bytes
#define EPI_LD  132

__device__ __forceinline__ void cp_chunk(
    uint32_t sbuf, int c, int tid,
    const __nv_bfloat16* Ah, const __nv_bfloat16* Al,
    const __nv_bfloat16* Bh, const __nv_bfloat16* Bl,
    int m0, int n0)
{
    const int k0 = c * BK;
    const __nv_bfloat16* srcs[4] = {Ah, Al, Bh, Bl};
#pragma unroll
    for (int t = 0; t < 4; t++) {
        const int row0 = (t < 2) ? m0 : n0;
        const __nv_bfloat16* src = srcs[t];
#pragma unroll
        for (int i = 0; i < 2; i++) {
            const int idx = tid + i * 256;       // 0..511
            const int r   = idx >> 2;            // 0..127
            const int seg = idx & 3;             // 0..3 (8 elems each)
            cp_async16(sbuf + t * TILE_B + (r * LDS_AB + seg * 8) * 2,
                       src + (size_t)(row0 + r) * EMB + k0 + seg * 8);
        }
    }
}

template <int MODE>
__global__ __launch_bounds__(256)
void gemm_wmma(const float* __restrict__ bias, float* __restrict__ C)
{
    extern __shared__ __align__(16) char smem[];
    const int tid  = threadIdx.x;
    const int wid  = tid >> 5;
    const int m0 = blockIdx.y * 128;
    const int n0 = blockIdx.x * 128;

    const __nv_bfloat16* Ah = (MODE == 1) ? g_ah : g_aoh;
    const __nv_bfloat16* Al = (MODE == 1) ? g_al : g_aol;
    const __nv_bfloat16* Bh = (MODE == 1) ? g_wh : g_ph;
    const __nv_bfloat16* Bl = (MODE == 1) ? g_wl : g_pl;

    const int warp_m = (wid & 3) * 32;   // 0,32,64,96
    const int warp_n = (wid >> 2) * 64;  // 0,64

    wmma::fragment<wmma::accumulator, 16, 16, 16, float> acc[2][4];
#pragma unroll
    for (int mt = 0; mt < 2; mt++)
#pragma unroll
        for (int nt = 0; nt < 4; nt++) wmma::fill_fragment(acc[mt][nt], 0.0f);

    const uint32_t sb = smem_u32(smem);

    // prologue
    cp_chunk(sb, 0, tid, Ah, Al, Bh, Bl, m0, n0);
    cp_commit();

    const int NCH = EMB / BK;   // 32
    for (int c = 0; c < NCH; c++) {
        if (c + 1 < NCH) {
            cp_chunk(sb + ((c + 1) & 1) * BUF_B, c + 1, tid, Ah, Al, Bh, Bl, m0, n0);
            cp_commit();
            cp_wait<1>();
        } else {
            cp_wait<0>();
        }
        __syncthreads();

        const __nv_bfloat16* buf =
            reinterpret_cast<const __nv_bfloat16*>(smem + (c & 1) * BUF_B);
        const __nv_bfloat16* sAh = buf;
        const __nv_bfloat16* sAl = buf + TILE_EL;
        const __nv_bfloat16* sBh = buf + 2 * TILE_EL;
        const __nv_bfloat16* sBl = buf + 3 * TILE_EL;

#pragma unroll
        for (int ks = 0; ks < BK; ks += 16) {
            wmma::fragment<wmma::matrix_a, 16, 16, 16, __nv_bfloat16,
                           wmma::row_major> ah[2], al[2];
            wmma::fragment<wmma::matrix_b, 16, 16, 16, __nv_bfloat16,
                           wmma::col_major> bh[4], bl[4];
#pragma unroll
            for (int mt = 0; mt < 2; mt++) {
                wmma::load_matrix_sync(ah[mt],
                    sAh + (warp_m + mt * 16) * LDS_AB + ks, LDS_AB);
                wmma::load_matrix_sync(al[mt],
                    sAl + (warp_m + mt * 16) * LDS_AB + ks, LDS_AB);
            }
#pragma unroll
            for (int nt = 0; nt < 4; nt++) {
                wmma::load_matrix_sync(bh[nt],
                    sBh + (warp_n + nt * 16) * LDS_AB + ks, LDS_AB);
                wmma::load_matrix_sync(bl[nt],
                    sBl + (warp_n + nt * 16) * LDS_AB + ks, LDS_AB);
            }
#pragma unroll
            for (int mt = 0; mt < 2; mt++)
#pragma unroll
                for (int nt = 0; nt < 4; nt++) {
                    wmma::mma_sync(acc[mt][nt], ah[mt], bh[nt], acc[mt][nt]);
                    wmma::mma_sync(acc[mt][nt], ah[mt], bl[nt], acc[mt][nt]);
                    wmma::mma_sync(acc[mt][nt], al[mt], bh[nt], acc[mt][nt]);
                }
        }
        __syncthreads();
    }

    // Epilogue: stage fp32 accumulators through smem, add bias, write out
    float* es = reinterpret_cast<float*>(smem);
#pragma unroll
    for (int mt = 0; mt < 2; mt++)
#pragma unroll
        for (int nt = 0; nt < 4; nt++)
            wmma::store_matrix_sync(
                es + (warp_m + mt * 16) * EPI_LD + warp_n + nt * 16,
                acc[mt][nt], EPI_LD, wmma::mem_row_major);
    __syncthreads();

#pragma unroll
    for (int i = 0; i < 16; i++) {
        const int idx  = tid + i * 256;      // over 128x32 float4 grid
        const int row  = idx >> 5;           // 0..127
        const int col4 = idx & 31;           // 0..31
        const int m = m0 + row;
        const int n = n0 + col4 * 4;
        const float4 bv = *reinterpret_cast<const float4*>(bias + n);
        float4 v;
        v.x = es[row * EPI_LD + col4 * 4 + 0] + bv.x;
        v.y = es[row * EPI_LD + col4 * 4 + 1] + bv.y;
        v.z = es[row * EPI_LD + col4 * 4 + 2] + bv.z;
        v.w = es[row * EPI_LD + col4 * 4 + 3] + bv.w;
        if (MODE == 1) {
            const int part = n >> 10;        // 0=q 1=k 2=v
            const int e    = n & 1023;
            const int h    = e >> 6;
            const int d    = e & 63;
            const int b    = m >> 11;
            const int s    = m & 2047;
            float* dst = (part == 0) ? g_q : (part == 1) ? g_k : g_v;
            *reinterpret_cast<float4*>(
                &dst[(((size_t)(b * HEADS + h) * SEQ) + s) * HD + d]) = v;
        } else {
            *reinterpret_cast<float4*>(&C[(size_t)m * EMB + n]) = v;
        }
    }
}

// ---------------------------------------------------------------------------
// RoPE in-place on g_q, g_k. One warp per (b,h,s) row.
// ---------------------------------------------------------------------------
__global__ __launch_bounds__(256)
void rope_kernel()
{
    const int warp = (blockIdx.x * blockDim.x + threadIdx.x) >> 5;
    const int lane = threadIdx.x & 31;
    if (warp >= BATCH * HEADS * SEQ) return;
    const int s = warp & (SEQ - 1);

    float* qp = g_q + (size_t)warp * HD;
    float* kp = g_k + (size_t)warp * HD;

    const float inv_freq = powf(10000.0f, -(float)(2 * lane) / (float)HD);
    float c, sn;
    sincosf((float)s * inv_freq, &sn, &c);

    float q1 = qp[lane], q2 = qp[lane + 32];
    qp[lane]      = q1 * c - q2 * sn;
    qp[lane + 32] = q2 * c + q1 * sn;

    float k1 = kp[lane], k2 = kp[lane + 32];
    kp[lane]      = k1 * c - k2 * sn;
    kp[lane + 32] = k2 * c + k1 * sn;
}

// ---------------------------------------------------------------------------
// Flash attention (fp32 FFMA). grid = (S/64, B*H), 256 threads.
// Writes output as bf16 (hi,lo) split directly into g_aoh/g_aol.
// ---------------------------------------------------------------------------
#define PS_LD 68
#define ATTN_SMEM ((64 * 64 * 3 + 64 * PS_LD) * 4)

__global__ __launch_bounds__(256)
void attn_kernel()
{
    extern __shared__ float sm[];
    float* Qt = sm;                 // [64][64]  Qt[d][r]
    float* Kt = Qt + 64 * 64;       // [64][64]  Kt[d][c]
    float* Ps = Kt + 64 * 64;       // [64][68]
    float* Vs = Ps + 64 * PS_LD;    // [64][64]  Vs[c][d]

    const int tid  = threadIdx.x;
    const int qb   = blockIdx.x;
    const int head = blockIdx.y;    // b*HEADS + h
    const int tx   = tid & 15;
    const int ty   = tid >> 4;

    const float scale = 0.125f;     // 1/sqrt(64)

    const float* Q = g_q + ((size_t)head * SEQ + qb * 64) * HD;
    const float* K = g_k + (size_t)head * SEQ * HD;
    const float* V = g_v + (size_t)head * SEQ * HD;

    {
        const int r  = tid >> 2;
        const int d0 = (tid & 3) * 16;
#pragma unroll
        for (int u = 0; u < 16; u += 4) {
            float4 v = *reinterpret_cast<const float4*>(Q + r * HD + d0 + u);
            Qt[(d0 + u + 0) * 64 + r] = v.x * scale;
            Qt[(d0 + u + 1) * 64 + r] = v.y * scale;
            Qt[(d0 + u + 2) * 64 + r] = v.z * scale;
            Qt[(d0 + u + 3) * 64 + r] = v.w * scale;
        }
    }

    float m_run[4], l_run[4], o[4][4];
#pragma unroll
    for (int i = 0; i < 4; i++) {
        m_run[i] = -1e30f; l_run[i] = 0.0f;
#pragma unroll
        for (int j = 0; j < 4; j++) o[i][j] = 0.0f;
    }

    for (int kb = 0; kb < SEQ / 64; kb++) {
        const float* Kb = K + kb * 64 * HD;
        const float* Vb = V + kb * 64 * HD;
        {
            const int r  = tid >> 2;
            const int d0 = (tid & 3) * 16;
#pragma unroll
            for (int u = 0; u < 16; u += 4) {
                float4 v = *reinterpret_cast<const float4*>(Kb + r * HD + d0 + u);
                Kt[(d0 + u + 0) * 64 + r] = v.x;
                Kt[(d0 + u + 1) * 64 + r] = v.y;
                Kt[(d0 + u + 2) * 64 + r] = v.z;
                Kt[(d0 + u + 3) * 64 + r] = v.w;
            }
            for (int u = tid * 4; u < 64 * 64; u += 1024)
                *reinterpret_cast<float4*>(Vs + u) =
                    *reinterpret_cast<const float4*>(Vb + u);
        }
        __syncthreads();

        float acc[4][4];
#pragma unroll
        for (int i = 0; i < 4; i++)
#pragma unroll
            for (int j = 0; j < 4; j++) acc[i][j] = 0.0f;

#pragma unroll 8
        for (int k = 0; k < 64; k++) {
            float4 a = *reinterpret_cast<const float4*>(&Qt[k * 64 + ty * 4]);
            float4 b = *reinterpret_cast<const float4*>(&Kt[k * 64 + tx * 4]);
            float ra[4] = {a.x, a.y, a.z, a.w};
            float rb[4] = {b.x, b.y, b.z, b.w};
#pragma unroll
            for (int i = 0; i < 4; i++)
#pragma unroll
                for (int j = 0; j < 4; j++)
                    acc[i][j] = fmaf(ra[i], rb[j], acc[i][j]);
        }

#pragma unroll
        for (int i = 0; i < 4; i++) {
            float mx = fmaxf(fmaxf(acc[i][0], acc[i][1]),
                             fmaxf(acc[i][2], acc[i][3]));
#pragma unroll
            for (int off = 8; off > 0; off >>= 1)
                mx = fmaxf(mx, __shfl_xor_sync(0xffffffffu, mx, off, 16));
            const float mnew = fmaxf(m_run[i], mx);
            const float corr = __expf(m_run[i] - mnew);
            float rs = 0.0f;
#pragma unroll
            for (int j = 0; j < 4; j++) {
                acc[i][j] = __expf(acc[i][j] - mnew);
                rs += acc[i][j];
            }
#pragma unroll
            for (int off = 8; off > 0; off >>= 1)
                rs += __shfl_xor_sync(0xffffffffu, rs, off, 16);
            l_run[i] = l_run[i] * corr + rs;
            m_run[i] = mnew;
#pragma unroll
            for (int j = 0; j < 4; j++) o[i][j] *= corr;
            *reinterpret_cast<float4*>(&Ps[(ty * 4 + i) * PS_LD + tx * 4]) =
                make_float4(acc[i][0], acc[i][1], acc[i][2], acc[i][3]);
        }
        __syncthreads();

#pragma unroll 8
        for (int c = 0; c < 64; c++) {
            float p0 = Ps[(ty * 4 + 0) * PS_LD + c];
            float p1 = Ps[(ty * 4 + 1) * PS_LD + c];
            float p2 = Ps[(ty * 4 + 2) * PS_LD + c];
            float p3 = Ps[(ty * 4 + 3) * PS_LD + c];
            float4 vv = *reinterpret_cast<const float4*>(&Vs[c * 64 + tx * 4]);
            o[0][0] = fmaf(p0, vv.x, o[0][0]); o[0][1] = fmaf(p0, vv.y, o[0][1]);
            o[0][2] = fmaf(p0, vv.z, o[0][2]); o[0][3] = fmaf(p0, vv.w, o[0][3]);
            o[1][0] = fmaf(p1, vv.x, o[1][0]); o[1][1] = fmaf(p1, vv.y, o[1][1]);
            o[1][2] = fmaf(p1, vv.z, o[1][2]); o[1][3] = fmaf(p1, vv.w, o[1][3]);
            o[2][0] = fmaf(p2, vv.x, o[2][0]); o[2][1] = fmaf(p2, vv.y, o[2][1]);
            o[2][2] = fmaf(p2, vv.z, o[2][2]); o[2][3] = fmaf(p2, vv.w, o[2][3]);
            o[3][0] = fmaf(p3, vv.x, o[3][0]); o[3][1] = fmaf(p3, vv.y, o[3][1]);
            o[3][2] = fmaf(p3, vv.z, o[3][2]); o[3][3] = fmaf(p3, vv.w, o[3][3]);
        }
        __syncthreads();
    }

    // write out as bf16 (hi,lo) split into [B*S, E] layout
    const int b = head >> 4;
    const int h = head & 15;
#pragma unroll
    for (int i = 0; i < 4; i++) {
        const float inv_l = 1.0f / l_run[i];
        const int s = qb * 64 + ty * 4 + i;
        const size_t base = (size_t)(b * SEQ + s) * EMB + h * HD + tx * 4;
        float v0 = o[i][0] * inv_l, v1 = o[i][1] * inv_l;
        float v2 = o[i][2] * inv_l, v3 = o[i][3] * inv_l;
        __nv_bfloat16 h0 = __float2bfloat16_rn(v0);
        __nv_bfloat16 h1 = __float2bfloat16_rn(v1);
        __nv_bfloat16 h2 = __float2bfloat16_rn(v2);
        __nv_bfloat16 h3 = __float2bfloat16_rn(v3);
        __nv_bfloat16 l0 = __float2bfloat16_rn(v0 - __bfloat162float(h0));
        __nv_bfloat16 l1 = __float2bfloat16_rn(v1 - __bfloat162float(h1));
        __nv_bfloat16 l2 = __float2bfloat16_rn(v2 - __bfloat162float(h2));
        __nv_bfloat16 l3 = __float2bfloat16_rn(v3 - __bfloat162float(h3));
        __nv_bfloat162* hp = reinterpret_cast<__nv_bfloat162*>(g_aoh + base);
        __nv_bfloat162* lp = reinterpret_cast<__nv_bfloat162*>(g_aol + base);
        hp[0] = __halves2bfloat162(h0, h1);
        hp[1] = __halves2bfloat162(h2, h3);
        lp[0] = __halves2bfloat162(l0, l1);
        lp[1] = __halves2bfloat162(l2, l3);
    }
}

// ---------------------------------------------------------------------------
extern "C" void kernel_launch(void* const* d_in, const int* in_sizes, int n_in,
                              void* d_out, int out_size)
{
    const float* hidden = (const float*)d_in[0];
    const float* qkv_w  = (const float*)d_in[1];
    const float* qkv_b  = (const float*)d_in[2];
    const float* proj_w = (const float*)d_in[3];
    const float* proj_b = (const float*)d_in[4];
    float* out = (float*)d_out;

    // 0) split fp32 -> bf16 hi/lo
    split_kernel<0><<<(MROWS * EMB / 4 + 255) / 256, 256>>>(hidden, MROWS * EMB / 4);
    split_kernel<1><<<(QKVN * EMB / 4 + 255) / 256, 256>>>(qkv_w, QKVN * EMB / 4);
    split_kernel<2><<<(EMB * EMB / 4 + 255) / 256, 256>>>(proj_w, EMB * EMB / 4);

    // 1) QKV GEMM (WMMA split bf16) + scatter
    cudaFuncSetAttribute(gemm_wmma<1>,
                         cudaFuncAttributeMaxDynamicSharedMemorySize, GSMEM);
    gemm_wmma<1><<<dim3(QKVN / 128, MROWS / 128), 256, GSMEM>>>(qkv_b, nullptr);

    // 2) RoPE in place on q,k
    rope_kernel<<<(BATCH * HEADS * SEQ + 7) / 8, 256>>>();

    // 3) flash attention (fp32), writes bf16 split output
    cudaFuncSetAttribute(attn_kernel,
                         cudaFuncAttributeMaxDynamicSharedMemorySize, ATTN_SMEM);
    attn_kernel<<<dim3(SEQ / 64, BATCH * HEADS), 256, ATTN_SMEM>>>();

    // 4) output projection (WMMA split bf16)
    cudaFuncSetAttribute(gemm_wmma<2>,
                         cudaFuncAttributeMaxDynamicSharedMemorySize, GSMEM);
    gemm_wmma<2><<<dim3(EMB / 128, MROWS / 128), 256, GSMEM>>>(proj_b, out);
}

// round 10
// speedup vs baseline: 1.9993x; 1.9993x over previous
#include <cuda_runtime.h>
#include <cuda_bf16.h>
#include <mma.h>
#include <math.h>
#include <stdint.h>

using namespace nvcuda;

// Problem constants
#define BATCH 4
#define SEQ   2048
#define EMB   1024
#define HEADS 16
#define HD    64
#define MROWS (BATCH * SEQ)          // 8192
#define QKVN  (3 * EMB)              // 3072

// ---------------------------------------------------------------------------
// Device-global scratch
// ---------------------------------------------------------------------------
__device__ float g_q[BATCH * HEADS * SEQ * HD];   // [B,H,S,hd] fp32 (pre-rope)
__device__ float g_k[BATCH * HEADS * SEQ * HD];
__device__ float g_v[BATCH * HEADS * SEQ * HD];

// bf16 split operand buffers for GEMMs
__device__ __nv_bfloat16 g_ah[MROWS * EMB], g_al[MROWS * EMB];   // hidden
__device__ __nv_bfloat16 g_wh[QKVN * EMB],  g_wl[QKVN * EMB];    // qkv_w
__device__ __nv_bfloat16 g_ph[EMB * EMB],   g_pl[EMB * EMB];     // proj_w
__device__ __nv_bfloat16 g_aoh[MROWS * EMB], g_aol[MROWS * EMB]; // attn out

// bf16 split attention operands
__device__ __nv_bfloat16 g_qh[BATCH * HEADS * SEQ * HD], g_ql[BATCH * HEADS * SEQ * HD];
__device__ __nv_bfloat16 g_kh[BATCH * HEADS * SEQ * HD], g_kl[BATCH * HEADS * SEQ * HD];
__device__ __nv_bfloat16 g_vth[BATCH * HEADS * HD * SEQ], g_vtl[BATCH * HEADS * HD * SEQ]; // [B,H,hd,S]

// ---------------------------------------------------------------------------
// helpers
// ---------------------------------------------------------------------------
__device__ __forceinline__ uint32_t smem_u32(const void* p) {
    uint32_t a;
    asm("{ .reg .u64 t; cvta.to.shared.u64 t, %1; cvt.u32.u64 %0, t; }"
        : "=r"(a) : "l"(p));
    return a;
}
__device__ __forceinline__ void cp_async16(uint32_t dst, const void* src) {
    asm volatile("cp.async.cg.shared.global [%0], [%1], 16;"
                 :: "r"(dst), "l"(src) : "memory");
}
__device__ __forceinline__ void cp_commit() {
    asm volatile("cp.async.commit_group;" ::: "memory");
}
template <int N>
__device__ __forceinline__ void cp_wait() {
    asm volatile("cp.async.wait_group %0;" :: "n"(N) : "memory");
}
// D += A*B, m16n8k16 row.col bf16 -> f32
__device__ __forceinline__ void mma16816(float* d, const uint32_t* a,
                                         uint32_t b0, uint32_t b1) {
    asm volatile(
        "mma.sync.aligned.m16n8k16.row.col.f32.bf16.bf16.f32 "
        "{%0,%1,%2,%3}, {%4,%5,%6,%7}, {%8,%9}, {%0,%1,%2,%3};"
        : "+f"(d[0]), "+f"(d[1]), "+f"(d[2]), "+f"(d[3])
        : "r"(a[0]), "r"(a[1]), "r"(a[2]), "r"(a[3]), "r"(b0), "r"(b1));
}
// pack two f32 into bf16x2 (lo in low half)
__device__ __forceinline__ uint32_t pack_bf16x2(float lo, float hi) {
    uint32_t r;
    asm("cvt.rn.bf16x2.f32 %0, %1, %2;" : "=r"(r) : "f"(hi), "f"(lo));
    return r;
}
__device__ __forceinline__ float bres(float f) {
    return f - __bfloat162float(__float2bfloat16_rn(f));
}

// ---------------------------------------------------------------------------
// fp32 -> (bf16 hi, bf16 lo) split conversion.  WHICH: 0=hidden 1=qkv_w 2=proj_w
// ---------------------------------------------------------------------------
template <int WHICH>
__global__ __launch_bounds__(256)
void split_kernel(const float* __restrict__ x, int n4)
{
    __nv_bfloat16* hi = (WHICH == 0) ? g_ah : (WHICH == 1) ? g_wh : g_ph;
    __nv_bfloat16* lo = (WHICH == 0) ? g_al : (WHICH == 1) ? g_wl : g_pl;
    int i = blockIdx.x * 256 + threadIdx.x;
    if (i >= n4) return;
    float4 v = reinterpret_cast<const float4*>(x)[i];
    __nv_bfloat16 h0 = __float2bfloat16_rn(v.x);
    __nv_bfloat16 h1 = __float2bfloat16_rn(v.y);
    __nv_bfloat16 h2 = __float2bfloat16_rn(v.z);
    __nv_bfloat16 h3 = __float2bfloat16_rn(v.w);
    __nv_bfloat16 l0 = __float2bfloat16_rn(v.x - __bfloat162float(h0));
    __nv_bfloat16 l1 = __float2bfloat16_rn(v.y - __bfloat162float(h1));
    __nv_bfloat16 l2 = __float2bfloat16_rn(v.z - __bfloat162float(h2));
    __nv_bfloat16 l3 = __float2bfloat16_rn(v.w - __bfloat162float(h3));
    __nv_bfloat162* hp = reinterpret_cast<__nv_bfloat162*>(hi) + 2 * i;
    __nv_bfloat162* lp = reinterpret_cast<__nv_bfloat162*>(lo) + 2 * i;
    hp[0] = __halves2bfloat162(h0, h1);
    hp[1] = __halves2bfloat162(h2, h3);
    lp[0] = __halves2bfloat162(l0, l1);
    lp[1] = __halves2bfloat162(l2, l3);
}

// ---------------------------------------------------------------------------
// WMMA split-bf16 GEMM (unchanged from R9)
// ---------------------------------------------------------------------------
#define BK      32
#define LDS_AB  40
#define TILE_EL (128 * LDS_AB)
#define TILE_B  (TILE_EL * 2)
#define BUF_B   (4 * TILE_B)
#define GSMEM   (2 * BUF_B)
#define EPI_LD  132

__device__ __forceinline__ void cp_chunk(
    uint32_t sbuf, int c, int tid,
    const __nv_bfloat16* Ah, const __nv_bfloat16* Al,
    const __nv_bfloat16* Bh, const __nv_bfloat16* Bl,
    int m0, int n0)
{
    const int k0 = c * BK;
    const __nv_bfloat16* srcs[4] = {Ah, Al, Bh, Bl};
#pragma unroll
    for (int t = 0; t < 4; t++) {
        const int row0 = (t < 2) ? m0 : n0;
        const __nv_bfloat16* src = srcs[t];
#pragma unroll
        for (int i = 0; i < 2; i++) {
            const int idx = tid + i * 256;
            const int r   = idx >> 2;
            const int seg = idx & 3;
            cp_async16(sbuf + t * TILE_B + (r * LDS_AB + seg * 8) * 2,
                       src + (size_t)(row0 + r) * EMB + k0 + seg * 8);
        }
    }
}

template <int MODE>
__global__ __launch_bounds__(256)
void gemm_wmma(const float* __restrict__ bias, float* __restrict__ C)
{
    extern __shared__ __align__(16) char smem[];
    const int tid  = threadIdx.x;
    const int wid  = tid >> 5;
    const int m0 = blockIdx.y * 128;
    const int n0 = blockIdx.x * 128;

    const __nv_bfloat16* Ah = (MODE == 1) ? g_ah : g_aoh;
    const __nv_bfloat16* Al = (MODE == 1) ? g_al : g_aol;
    const __nv_bfloat16* Bh = (MODE == 1) ? g_wh : g_ph;
    const __nv_bfloat16* Bl = (MODE == 1) ? g_wl : g_pl;

    const int warp_m = (wid & 3) * 32;
    const int warp_n = (wid >> 2) * 64;

    wmma::fragment<wmma::accumulator, 16, 16, 16, float> acc[2][4];
#pragma unroll
    for (int mt = 0; mt < 2; mt++)
#pragma unroll
        for (int nt = 0; nt < 4; nt++) wmma::fill_fragment(acc[mt][nt], 0.0f);

    const uint32_t sb = smem_u32(smem);
    cp_chunk(sb, 0, tid, Ah, Al, Bh, Bl, m0, n0);
    cp_commit();

    const int NCH = EMB / BK;
    for (int c = 0; c < NCH; c++) {
        if (c + 1 < NCH) {
            cp_chunk(sb + ((c + 1) & 1) * BUF_B, c + 1, tid, Ah, Al, Bh, Bl, m0, n0);
            cp_commit();
            cp_wait<1>();
        } else {
            cp_wait<0>();
        }
        __syncthreads();

        const __nv_bfloat16* buf =
            reinterpret_cast<const __nv_bfloat16*>(smem + (c & 1) * BUF_B);
        const __nv_bfloat16* sAh = buf;
        const __nv_bfloat16* sAl = buf + TILE_EL;
        const __nv_bfloat16* sBh = buf + 2 * TILE_EL;
        const __nv_bfloat16* sBl = buf + 3 * TILE_EL;

#pragma unroll
        for (int ks = 0; ks < BK; ks += 16) {
            wmma::fragment<wmma::matrix_a, 16, 16, 16, __nv_bfloat16,
                           wmma::row_major> ah[2], al[2];
            wmma::fragment<wmma::matrix_b, 16, 16, 16, __nv_bfloat16,
                           wmma::col_major> bh[4], bl[4];
#pragma unroll
            for (int mt = 0; mt < 2; mt++) {
                wmma::load_matrix_sync(ah[mt],
                    sAh + (warp_m + mt * 16) * LDS_AB + ks, LDS_AB);
                wmma::load_matrix_sync(al[mt],
                    sAl + (warp_m + mt * 16) * LDS_AB + ks, LDS_AB);
            }
#pragma unroll
            for (int nt = 0; nt < 4; nt++) {
                wmma::load_matrix_sync(bh[nt],
                    sBh + (warp_n + nt * 16) * LDS_AB + ks, LDS_AB);
                wmma::load_matrix_sync(bl[nt],
                    sBl + (warp_n + nt * 16) * LDS_AB + ks, LDS_AB);
            }
#pragma unroll
            for (int mt = 0; mt < 2; mt++)
#pragma unroll
                for (int nt = 0; nt < 4; nt++) {
                    wmma::mma_sync(acc[mt][nt], ah[mt], bh[nt], acc[mt][nt]);
                    wmma::mma_sync(acc[mt][nt], ah[mt], bl[nt], acc[mt][nt]);
                    wmma::mma_sync(acc[mt][nt], al[mt], bh[nt], acc[mt][nt]);
                }
        }
        __syncthreads();
    }

    float* es = reinterpret_cast<float*>(smem);
#pragma unroll
    for (int mt = 0; mt < 2; mt++)
#pragma unroll
        for (int nt = 0; nt < 4; nt++)
            wmma::store_matrix_sync(
                es + (warp_m + mt * 16) * EPI_LD + warp_n + nt * 16,
                acc[mt][nt], EPI_LD, wmma::mem_row_major);
    __syncthreads();

#pragma unroll
    for (int i = 0; i < 16; i++) {
        const int idx  = tid + i * 256;
        const int row  = idx >> 5;
        const int col4 = idx & 31;
        const int m = m0 + row;
        const int n = n0 + col4 * 4;
        const float4 bv = *reinterpret_cast<const float4*>(bias + n);
        float4 v;
        v.x = es[row * EPI_LD + col4 * 4 + 0] + bv.x;
        v.y = es[row * EPI_LD + col4 * 4 + 1] + bv.y;
        v.z = es[row * EPI_LD + col4 * 4 + 2] + bv.z;
        v.w = es[row * EPI_LD + col4 * 4 + 3] + bv.w;
        if (MODE == 1) {
            const int part = n >> 10;
            const int e    = n & 1023;
            const int h    = e >> 6;
            const int d    = e & 63;
            const int b    = m >> 11;
            const int s    = m & 2047;
            float* dst = (part == 0) ? g_q : (part == 1) ? g_k : g_v;
            *reinterpret_cast<float4*>(
                &dst[(((size_t)(b * HEADS + h) * SEQ) + s) * HD + d]) = v;
        } else {
            *reinterpret_cast<float4*>(&C[(size_t)m * EMB + n]) = v;
        }
    }
}

// ---------------------------------------------------------------------------
// RoPE + split: reads g_q/g_k fp32, writes bf16 hi/lo (q pre-scaled by 1/8).
// ---------------------------------------------------------------------------
__global__ __launch_bounds__(256)
void rope_split()
{
    const int warp = (blockIdx.x * blockDim.x + threadIdx.x) >> 5;
    const int lane = threadIdx.x & 31;
    if (warp >= BATCH * HEADS * SEQ) return;
    const int s = warp & (SEQ - 1);

    const float* qp = g_q + (size_t)warp * HD;
    const float* kp = g_k + (size_t)warp * HD;

    const float inv_freq = powf(10000.0f, -(float)(2 * lane) / (float)HD);
    float c, sn;
    sincosf((float)s * inv_freq, &sn, &c);

    float q1 = qp[lane], q2 = qp[lane + 32];
    float k1 = kp[lane], k2 = kp[lane + 32];
    float qa = (q1 * c - q2 * sn) * 0.125f;
    float qb = (q2 * c + q1 * sn) * 0.125f;
    float ka = k1 * c - k2 * sn;
    float kb = k2 * c + k1 * sn;

    const size_t base = (size_t)warp * HD;
    __nv_bfloat16 h;
    h = __float2bfloat16_rn(qa); g_qh[base + lane] = h;
    g_ql[base + lane] = __float2bfloat16_rn(qa - __bfloat162float(h));
    h = __float2bfloat16_rn(qb); g_qh[base + lane + 32] = h;
    g_ql[base + lane + 32] = __float2bfloat16_rn(qb - __bfloat162float(h));
    h = __float2bfloat16_rn(ka); g_kh[base + lane] = h;
    g_kl[base + lane] = __float2bfloat16_rn(ka - __bfloat162float(h));
    h = __float2bfloat16_rn(kb); g_kh[base + lane + 32] = h;
    g_kl[base + lane + 32] = __float2bfloat16_rn(kb - __bfloat162float(h));
}

// ---------------------------------------------------------------------------
// V prep: transpose [B,H,S,hd] fp32 -> [B,H,hd,S] bf16 hi/lo
// ---------------------------------------------------------------------------
__global__ __launch_bounds__(256)
void vprep()
{
    __shared__ float vs[64][65];
    const int tid  = threadIdx.x;
    const int sb   = blockIdx.x * 64;
    const int head = blockIdx.y;
    const float* V = g_v + ((size_t)head * SEQ + sb) * HD;
#pragma unroll
    for (int i = 0; i < 16; i++) {
        const int e = tid + i * 256;
        vs[e >> 6][e & 63] = V[(size_t)(e >> 6) * HD + (e & 63)];
    }
    __syncthreads();
    const int d  = tid >> 2;
    const int s4 = (tid & 3) * 16;
    __nv_bfloat16 hb[16], lb[16];
#pragma unroll
    for (int j = 0; j < 16; j++) {
        const float f = vs[s4 + j][d];
        const __nv_bfloat16 h = __float2bfloat16_rn(f);
        hb[j] = h;
        lb[j] = __float2bfloat16_rn(f - __bfloat162float(h));
    }
    const size_t base = (size_t)head * HD * SEQ + (size_t)d * SEQ + sb + s4;
    reinterpret_cast<uint4*>(g_vth + base)[0] = reinterpret_cast<uint4*>(hb)[0];
    reinterpret_cast<uint4*>(g_vth + base)[1] = reinterpret_cast<uint4*>(hb)[1];
    reinterpret_cast<uint4*>(g_vtl + base)[0] = reinterpret_cast<uint4*>(lb)[0];
    reinterpret_cast<uint4*>(g_vtl + base)[1] = reinterpret_cast<uint4*>(lb)[1];
}

// ---------------------------------------------------------------------------
// Tensor-core flash attention. grid=(SEQ/128, B*H), 256 threads (8 warps).
// Warp w owns q rows [qb*128 + w*16, +16). 3-term split QK^T and P*V.
// smem: double-buffered {Kh, Kl, Vth, Vtl}, each 64 rows x 72-elem stride.
// ---------------------------------------------------------------------------
#define AK_STR   72
#define ATILE_EL (64 * AK_STR)
#define ABUF_EL  (4 * ATILE_EL)
#define AT_SMEM  (2 * ABUF_EL * 2)      // 73728 bytes

__device__ __forceinline__ void attn_stage(uint32_t sb, int buf, int kb,
                                           size_t hbase, size_t vbase, int tid)
{
#pragma unroll
    for (int i = 0; i < 8; i++) {
        const int t  = i >> 1;                       // tile 0..3
        const int r  = (tid >> 3) + 32 * (i & 1);    // 0..63
        const int ch = tid & 7;                      // 16B chunk
        const __nv_bfloat16* src;
        if (t == 0)      src = g_kh  + hbase + (size_t)(kb * 64 + r) * HD + ch * 8;
        else if (t == 1) src = g_kl  + hbase + (size_t)(kb * 64 + r) * HD + ch * 8;
        else if (t == 2) src = g_vth + vbase + (size_t)r * SEQ + kb * 64 + ch * 8;
        else             src = g_vtl + vbase + (size_t)r * SEQ + kb * 64 + ch * 8;
        cp_async16(sb + (buf * ABUF_EL + t * ATILE_EL + r * AK_STR + ch * 8) * 2, src);
    }
}

__global__ __launch_bounds__(256)
void attn_mma()
{
    extern __shared__ __align__(16) __nv_bfloat16 sk[];
    const uint32_t sb = smem_u32(sk);
    const int tid  = threadIdx.x;
    const int wid  = tid >> 5;
    const int lane = tid & 31;
    const int gid  = lane >> 2;      // 0..7
    const int tidg = lane & 3;       // 0..3
    const int qb   = blockIdx.x;
    const int head = blockIdx.y;     // b*HEADS + h

    const size_t hbase = (size_t)head * SEQ * HD;
    const size_t vbase = (size_t)head * HD * SEQ;

    // Q A-fragments (held in registers for whole CTA lifetime)
    uint32_t qah[4][4], qal[4][4];
    {
        const int r0 = qb * 128 + wid * 16 + gid;
        const uint32_t* q0h = reinterpret_cast<const uint32_t*>(g_qh + hbase + (size_t)r0 * HD);
        const uint32_t* q1h = reinterpret_cast<const uint32_t*>(g_qh + hbase + (size_t)(r0 + 8) * HD);
        const uint32_t* q0l = reinterpret_cast<const uint32_t*>(g_ql + hbase + (size_t)r0 * HD);
        const uint32_t* q1l = reinterpret_cast<const uint32_t*>(g_ql + hbase + (size_t)(r0 + 8) * HD);
#pragma unroll
        for (int ks = 0; ks < 4; ks++) {
            qah[ks][0] = q0h[ks * 8 + tidg];
            qah[ks][1] = q1h[ks * 8 + tidg];
            qah[ks][2] = q0h[ks * 8 + tidg + 4];
            qah[ks][3] = q1h[ks * 8 + tidg + 4];
            qal[ks][0] = q0l[ks * 8 + tidg];
            qal[ks][1] = q1l[ks * 8 + tidg];
            qal[ks][2] = q0l[ks * 8 + tidg + 4];
            qal[ks][3] = q1l[ks * 8 + tidg + 4];
        }
    }

    float o[8][4];
#pragma unroll
    for (int nt = 0; nt < 8; nt++)
#pragma unroll
        for (int j = 0; j < 4; j++) o[nt][j] = 0.0f;
    float m0 = -1e30f, m1 = -1e30f, l0 = 0.0f, l1 = 0.0f;

    attn_stage(sb, 0, 0, hbase, vbase, tid);
    cp_commit();

    const int NKB = SEQ / 64;    // 32
    for (int kb = 0; kb < NKB; kb++) {
        if (kb + 1 < NKB) {
            attn_stage(sb, (kb + 1) & 1, kb + 1, hbase, vbase, tid);
            cp_commit();
            cp_wait<1>();
        } else {
            cp_wait<0>();
        }
        __syncthreads();

        const __nv_bfloat16* bs = sk + (kb & 1) * ABUF_EL;
        const __nv_bfloat16* Kh = bs;
        const __nv_bfloat16* Kl = bs + ATILE_EL;
        const __nv_bfloat16* Vh = bs + 2 * ATILE_EL;
        const __nv_bfloat16* Vl = bs + 3 * ATILE_EL;

        // ---- S = (Q/8) K^T, 3-term split ----
        float s[8][4];
#pragma unroll
        for (int nt = 0; nt < 8; nt++)
#pragma unroll
            for (int j = 0; j < 4; j++) s[nt][j] = 0.0f;

#pragma unroll
        for (int ks = 0; ks < 4; ks++) {
#pragma unroll
            for (int nt = 0; nt < 8; nt++) {
                const uint32_t* krh = reinterpret_cast<const uint32_t*>(
                    Kh + (nt * 8 + gid) * AK_STR);
                const uint32_t* krl = reinterpret_cast<const uint32_t*>(
                    Kl + (nt * 8 + gid) * AK_STR);
                const uint32_t bh0 = krh[8 * ks + tidg];
                const uint32_t bh1 = krh[8 * ks + tidg + 4];
                const uint32_t bl0 = krl[8 * ks + tidg];
                const uint32_t bl1 = krl[8 * ks + tidg + 4];
                mma16816(s[nt], qah[ks], bh0, bh1);
                mma16816(s[nt], qah[ks], bl0, bl1);
                mma16816(s[nt], qal[ks], bh0, bh1);
            }
        }

        // ---- online softmax on register tiles ----
        float mx0 = -1e30f, mx1 = -1e30f;
#pragma unroll
        for (int nt = 0; nt < 8; nt++) {
            mx0 = fmaxf(mx0, fmaxf(s[nt][0], s[nt][1]));
            mx1 = fmaxf(mx1, fmaxf(s[nt][2], s[nt][3]));
        }
        mx0 = fmaxf(mx0, __shfl_xor_sync(0xffffffffu, mx0, 1));
        mx0 = fmaxf(mx0, __shfl_xor_sync(0xffffffffu, mx0, 2));
        mx1 = fmaxf(mx1, __shfl_xor_sync(0xffffffffu, mx1, 1));
        mx1 = fmaxf(mx1, __shfl_xor_sync(0xffffffffu, mx1, 2));
        const float mn0 = fmaxf(m0, mx0), mn1 = fmaxf(m1, mx1);
        const float c0 = __expf(m0 - mn0), c1 = __expf(m1 - mn1);
        float rs0 = 0.0f, rs1 = 0.0f;
#pragma unroll
        for (int nt = 0; nt < 8; nt++) {
            s[nt][0] = __expf(s[nt][0] - mn0);
            s[nt][1] = __expf(s[nt][1] - mn0);
            s[nt][2] = __expf(s[nt][2] - mn1);
            s[nt][3] = __expf(s[nt][3] - mn1);
            rs0 += s[nt][0] + s[nt][1];
            rs1 += s[nt][2] + s[nt][3];
        }
        rs0 += __shfl_xor_sync(0xffffffffu, rs0, 1);
        rs0 += __shfl_xor_sync(0xffffffffu, rs0, 2);
        rs1 += __shfl_xor_sync(0xffffffffu, rs1, 1);
        rs1 += __shfl_xor_sync(0xffffffffu, rs1, 2);
        l0 = l0 * c0 + rs0;  l1 = l1 * c1 + rs1;
        m0 = mn0;  m1 = mn1;
#pragma unroll
        for (int nt = 0; nt < 8; nt++) {
            o[nt][0] *= c0; o[nt][1] *= c0;
            o[nt][2] *= c1; o[nt][3] *= c1;
        }

        // ---- O += P V, 3-term split; P converts C-layout -> A-layout in regs ----
#pragma unroll
        for (int ks = 0; ks < 4; ks++) {
            uint32_t pah[4], pal[4];
            pah[0] = pack_bf16x2(s[2 * ks][0], s[2 * ks][1]);
            pah[1] = pack_bf16x2(s[2 * ks][2], s[2 * ks][3]);
            pah[2] = pack_bf16x2(s[2 * ks + 1][0], s[2 * ks + 1][1]);
            pah[3] = pack_bf16x2(s[2 * ks + 1][2], s[2 * ks + 1][3]);
            pal[0] = pack_bf16x2(bres(s[2 * ks][0]), bres(s[2 * ks][1]));
            pal[1] = pack_bf16x2(bres(s[2 * ks][2]), bres(s[2 * ks][3]));
            pal[2] = pack_bf16x2(bres(s[2 * ks + 1][0]), bres(s[2 * ks + 1][1]));
            pal[3] = pack_bf16x2(bres(s[2 * ks + 1][2]), bres(s[2 * ks + 1][3]));
#pragma unroll
            for (int nt = 0; nt < 8; nt++) {
                const uint32_t* vrh = reinterpret_cast<const uint32_t*>(
                    Vh + (nt * 8 + gid) * AK_STR);
                const uint32_t* vrl = reinterpret_cast<const uint32_t*>(
                    Vl + (nt * 8 + gid) * AK_STR);
                const uint32_t bh0 = vrh[8 * ks + tidg];
                const uint32_t bh1 = vrh[8 * ks + tidg + 4];
                const uint32_t bl0 = vrl[8 * ks + tidg];
                const uint32_t bl1 = vrl[8 * ks + tidg + 4];
                mma16816(o[nt], pah, bh0, bh1);
                mma16816(o[nt], pah, bl0, bl1);
                mma16816(o[nt], pal, bh0, bh1);
            }
        }
        __syncthreads();
    }

    // ---- epilogue: normalize, split to bf16 hi/lo, write [B*S, E] ----
    const float i0 = 1.0f / l0, i1 = 1.0f / l1;
    const int b = head >> 4, h = head & 15;
    const int s0 = qb * 128 + wid * 16;
#pragma unroll
    for (int nt = 0; nt < 8; nt++) {
        const float f0 = o[nt][0] * i0, f1 = o[nt][1] * i0;
        const float f2 = o[nt][2] * i1, f3 = o[nt][3] * i1;
        const size_t base0 = (size_t)(b * SEQ + s0 + gid) * EMB +
                             h * 64 + nt * 8 + 2 * tidg;
        const size_t base1 = (size_t)(b * SEQ + s0 + gid + 8) * EMB +
                             h * 64 + nt * 8 + 2 * tidg;
        *reinterpret_cast<uint32_t*>(g_aoh + base0) = pack_bf16x2(f0, f1);
        *reinterpret_cast<uint32_t*>(g_aol + base0) = pack_bf16x2(bres(f0), bres(f1));
        *reinterpret_cast<uint32_t*>(g_aoh + base1) = pack_bf16x2(f2, f3);
        *reinterpret_cast<uint32_t*>(g_aol + base1) = pack_bf16x2(bres(f2), bres(f3));
    }
}

// ---------------------------------------------------------------------------
extern "C" void kernel_launch(void* const* d_in, const int* in_sizes, int n_in,
                              void* d_out, int out_size)
{
    const float* hidden = (const float*)d_in[0];
    const float* qkv_w  = (const float*)d_in[1];
    const float* qkv_b  = (const float*)d_in[2];
    const float* proj_w = (const float*)d_in[3];
    const float* proj_b = (const float*)d_in[4];
    float* out = (float*)d_out;

    // 0) split fp32 -> bf16 hi/lo
    split_kernel<0><<<(MROWS * EMB / 4 + 255) / 256, 256>>>(hidden, MROWS * EMB / 4);
    split_kernel<1><<<(QKVN * EMB / 4 + 255) / 256, 256>>>(qkv_w, QKVN * EMB / 4);
    split_kernel<2><<<(EMB * EMB / 4 + 255) / 256, 256>>>(proj_w, EMB * EMB / 4);

    // 1) QKV GEMM (WMMA split bf16) + scatter to q/k/v fp32
    cudaFuncSetAttribute(gemm_wmma<1>,
                         cudaFuncAttributeMaxDynamicSharedMemorySize, GSMEM);
    gemm_wmma<1><<<dim3(QKVN / 128, MROWS / 128), 256, GSMEM>>>(qkv_b, nullptr);

    // 2) RoPE + bf16 split of q,k ; transpose+split of v
    rope_split<<<(BATCH * HEADS * SEQ + 7) / 8, 256>>>();
    vprep<<<dim3(SEQ / 64, BATCH * HEADS), 256>>>();

    // 3) tensor-core flash attention (split bf16), writes split output
    cudaFuncSetAttribute(attn_mma,
                         cudaFuncAttributeMaxDynamicSharedMemorySize, AT_SMEM);
    attn_mma<<<dim3(SEQ / 128, BATCH * HEADS), 256, AT_SMEM>>>();

    // 4) output projection (WMMA split bf16)
    cudaFuncSetAttribute(gemm_wmma<2>,
                         cudaFuncAttributeMaxDynamicSharedMemorySize, GSMEM);
    gemm_wmma<2><<<dim3(EMB / 128, MROWS / 128), 256, GSMEM>>>(proj_b, out);
}

// round 11
// speedup vs baseline: 1.9996x; 1.0002x over previous
#include <cuda_runtime.h>
#include <cuda_bf16.h>
#include <mma.h>
#include <math.h>
#include <stdint.h>

using namespace nvcuda;

// Problem constants
#define BATCH 4
#define SEQ   2048
#define EMB   1024
#define HEADS 16
#define HD    64
#define MROWS (BATCH * SEQ)          // 8192
#define QKVN  (3 * EMB)              // 3072

// ---------------------------------------------------------------------------
// Device-global scratch
// ---------------------------------------------------------------------------
__device__ float g_q[BATCH * HEADS * SEQ * HD];   // [B,H,S,hd] fp32 (pre-rope)
__device__ float g_k[BATCH * HEADS * SEQ * HD];
__device__ float g_v[BATCH * HEADS * SEQ * HD];

// bf16 split operand buffers for GEMMs
__device__ __nv_bfloat16 g_ah[MROWS * EMB], g_al[MROWS * EMB];   // hidden
__device__ __nv_bfloat16 g_wh[QKVN * EMB],  g_wl[QKVN * EMB];    // qkv_w
__device__ __nv_bfloat16 g_ph[EMB * EMB],   g_pl[EMB * EMB];     // proj_w
__device__ __nv_bfloat16 g_aoh[MROWS * EMB], g_aol[MROWS * EMB]; // attn out

// bf16 split attention operands
__device__ __nv_bfloat16 g_qh[BATCH * HEADS * SEQ * HD], g_ql[BATCH * HEADS * SEQ * HD];
__device__ __nv_bfloat16 g_kh[BATCH * HEADS * SEQ * HD], g_kl[BATCH * HEADS * SEQ * HD];
__device__ __nv_bfloat16 g_vth[BATCH * HEADS * HD * SEQ], g_vtl[BATCH * HEADS * HD * SEQ]; // [B,H,hd,S]

// ---------------------------------------------------------------------------
// helpers
// ---------------------------------------------------------------------------
__device__ __forceinline__ uint32_t smem_u32(const void* p) {
    uint32_t a;
    asm("{ .reg .u64 t; cvta.to.shared.u64 t, %1; cvt.u32.u64 %0, t; }"
        : "=r"(a) : "l"(p));
    return a;
}
__device__ __forceinline__ void cp_async16(uint32_t dst, const void* src) {
    asm volatile("cp.async.cg.shared.global [%0], [%1], 16;"
                 :: "r"(dst), "l"(src) : "memory");
}
__device__ __forceinline__ void cp_commit() {
    asm volatile("cp.async.commit_group;" ::: "memory");
}
template <int N>
__device__ __forceinline__ void cp_wait() {
    asm volatile("cp.async.wait_group %0;" :: "n"(N) : "memory");
}
// D += A*B, m16n8k16 row.col bf16 -> f32
__device__ __forceinline__ void mma16816(float* d, const uint32_t* a,
                                         uint32_t b0, uint32_t b1) {
    asm volatile(
        "mma.sync.aligned.m16n8k16.row.col.f32.bf16.bf16.f32 "
        "{%0,%1,%2,%3}, {%4,%5,%6,%7}, {%8,%9}, {%0,%1,%2,%3};"
        : "+f"(d[0]), "+f"(d[1]), "+f"(d[2]), "+f"(d[3])
        : "r"(a[0]), "r"(a[1]), "r"(a[2]), "r"(a[3]), "r"(b0), "r"(b1));
}
// pack two f32 into bf16x2 (lo in low half)
__device__ __forceinline__ uint32_t pack_bf16x2(float lo, float hi) {
    uint32_t r;
    asm("cvt.rn.bf16x2.f32 %0, %1, %2;" : "=r"(r) : "f"(hi), "f"(lo));
    return r;
}
__device__ __forceinline__ float bres(float f) {
    return f - __bfloat162float(__float2bfloat16_rn(f));
}

// ---------------------------------------------------------------------------
// fp32 -> (bf16 hi, bf16 lo) split conversion.  WHICH: 0=hidden 1=qkv_w 2=proj_w
// ---------------------------------------------------------------------------
template <int WHICH>
__global__ __launch_bounds__(256)
void split_kernel(const float* __restrict__ x, int n4)
{
    __nv_bfloat16* hi = (WHICH == 0) ? g_ah : (WHICH == 1) ? g_wh : g_ph;
    __nv_bfloat16* lo = (WHICH == 0) ? g_al : (WHICH == 1) ? g_wl : g_pl;
    int i = blockIdx.x * 256 + threadIdx.x;
    if (i >= n4) return;
    float4 v = reinterpret_cast<const float4*>(x)[i];
    __nv_bfloat16 h0 = __float2bfloat16_rn(v.x);
    __nv_bfloat16 h1 = __float2bfloat16_rn(v.y);
    __nv_bfloat16 h2 = __float2bfloat16_rn(v.z);
    __nv_bfloat16 h3 = __float2bfloat16_rn(v.w);
    __nv_bfloat16 l0 = __float2bfloat16_rn(v.x - __bfloat162float(h0));
    __nv_bfloat16 l1 = __float2bfloat16_rn(v.y - __bfloat162float(h1));
    __nv_bfloat16 l2 = __float2bfloat16_rn(v.z - __bfloat162float(h2));
    __nv_bfloat16 l3 = __float2bfloat16_rn(v.w - __bfloat162float(h3));
    __nv_bfloat162* hp = reinterpret_cast<__nv_bfloat162*>(hi) + 2 * i;
    __nv_bfloat162* lp = reinterpret_cast<__nv_bfloat162*>(lo) + 2 * i;
    hp[0] = __halves2bfloat162(h0, h1);
    hp[1] = __halves2bfloat162(h2, h3);
    lp[0] = __halves2bfloat162(l0, l1);
    lp[1] = __halves2bfloat162(l2, l3);
}

// ---------------------------------------------------------------------------
// WMMA split-bf16 GEMM (unchanged from R9)
// ---------------------------------------------------------------------------
#define BK      32
#define LDS_AB  40
#define TILE_EL (128 * LDS_AB)
#define TILE_B  (TILE_EL * 2)
#define BUF_B   (4 * TILE_B)
#define GSMEM   (2 * BUF_B)
#define EPI_LD  132

__device__ __forceinline__ void cp_chunk(
    uint32_t sbuf, int c, int tid,
    const __nv_bfloat16* Ah, const __nv_bfloat16* Al,
    const __nv_bfloat16* Bh, const __nv_bfloat16* Bl,
    int m0, int n0)
{
    const int k0 = c * BK;
    const __nv_bfloat16* srcs[4] = {Ah, Al, Bh, Bl};
#pragma unroll
    for (int t = 0; t < 4; t++) {
        const int row0 = (t < 2) ? m0 : n0;
        const __nv_bfloat16* src = srcs[t];
#pragma unroll
        for (int i = 0; i < 2; i++) {
            const int idx = tid + i * 256;
            const int r   = idx >> 2;
            const int seg = idx & 3;
            cp_async16(sbuf + t * TILE_B + (r * LDS_AB + seg * 8) * 2,
                       src + (size_t)(row0 + r) * EMB + k0 + seg * 8);
        }
    }
}

template <int MODE>
__global__ __launch_bounds__(256)
void gemm_wmma(const float* __restrict__ bias, float* __restrict__ C)
{
    extern __shared__ __align__(16) char smem[];
    const int tid  = threadIdx.x;
    const int wid  = tid >> 5;
    const int m0 = blockIdx.y * 128;
    const int n0 = blockIdx.x * 128;

    const __nv_bfloat16* Ah = (MODE == 1) ? g_ah : g_aoh;
    const __nv_bfloat16* Al = (MODE == 1) ? g_al : g_aol;
    const __nv_bfloat16* Bh = (MODE == 1) ? g_wh : g_ph;
    const __nv_bfloat16* Bl = (MODE == 1) ? g_wl : g_pl;

    const int warp_m = (wid & 3) * 32;
    const int warp_n = (wid >> 2) * 64;

    wmma::fragment<wmma::accumulator, 16, 16, 16, float> acc[2][4];
#pragma unroll
    for (int mt = 0; mt < 2; mt++)
#pragma unroll
        for (int nt = 0; nt < 4; nt++) wmma::fill_fragment(acc[mt][nt], 0.0f);

    const uint32_t sb = smem_u32(smem);
    cp_chunk(sb, 0, tid, Ah, Al, Bh, Bl, m0, n0);
    cp_commit();

    const int NCH = EMB / BK;
    for (int c = 0; c < NCH; c++) {
        if (c + 1 < NCH) {
            cp_chunk(sb + ((c + 1) & 1) * BUF_B, c + 1, tid, Ah, Al, Bh, Bl, m0, n0);
            cp_commit();
            cp_wait<1>();
        } else {
            cp_wait<0>();
        }
        __syncthreads();

        const __nv_bfloat16* buf =
            reinterpret_cast<const __nv_bfloat16*>(smem + (c & 1) * BUF_B);
        const __nv_bfloat16* sAh = buf;
        const __nv_bfloat16* sAl = buf + TILE_EL;
        const __nv_bfloat16* sBh = buf + 2 * TILE_EL;
        const __nv_bfloat16* sBl = buf + 3 * TILE_EL;

#pragma unroll
        for (int ks = 0; ks < BK; ks += 16) {
            wmma::fragment<wmma::matrix_a, 16, 16, 16, __nv_bfloat16,
                           wmma::row_major> ah[2], al[2];
            wmma::fragment<wmma::matrix_b, 16, 16, 16, __nv_bfloat16,
                           wmma::col_major> bh[4], bl[4];
#pragma unroll
            for (int mt = 0; mt < 2; mt++) {
                wmma::load_matrix_sync(ah[mt],
                    sAh + (warp_m + mt * 16) * LDS_AB + ks, LDS_AB);
                wmma::load_matrix_sync(al[mt],
                    sAl + (warp_m + mt * 16) * LDS_AB + ks, LDS_AB);
            }
#pragma unroll
            for (int nt = 0; nt < 4; nt++) {
                wmma::load_matrix_sync(bh[nt],
                    sBh + (warp_n + nt * 16) * LDS_AB + ks, LDS_AB);
                wmma::load_matrix_sync(bl[nt],
                    sBl + (warp_n + nt * 16) * LDS_AB + ks, LDS_AB);
            }
#pragma unroll
            for (int mt = 0; mt < 2; mt++)
#pragma unroll
                for (int nt = 0; nt < 4; nt++) {
                    wmma::mma_sync(acc[mt][nt], ah[mt], bh[nt], acc[mt][nt]);
                    wmma::mma_sync(acc[mt][nt], ah[mt], bl[nt], acc[mt][nt]);
                    wmma::mma_sync(acc[mt][nt], al[mt], bh[nt], acc[mt][nt]);
                }
        }
        __syncthreads();
    }

    float* es = reinterpret_cast<float*>(smem);
#pragma unroll
    for (int mt = 0; mt < 2; mt++)
#pragma unroll
        for (int nt = 0; nt < 4; nt++)
            wmma::store_matrix_sync(
                es + (warp_m + mt * 16) * EPI_LD + warp_n + nt * 16,
                acc[mt][nt], EPI_LD, wmma::mem_row_major);
    __syncthreads();

#pragma unroll
    for (int i = 0; i < 16; i++) {
        const int idx  = tid + i * 256;
        const int row  = idx >> 5;
        const int col4 = idx & 31;
        const int m = m0 + row;
        const int n = n0 + col4 * 4;
        const float4 bv = *reinterpret_cast<const float4*>(bias + n);
        float4 v;
        v.x = es[row * EPI_LD + col4 * 4 + 0] + bv.x;
        v.y = es[row * EPI_LD + col4 * 4 + 1] + bv.y;
        v.z = es[row * EPI_LD + col4 * 4 + 2] + bv.z;
        v.w = es[row * EPI_LD + col4 * 4 + 3] + bv.w;
        if (MODE == 1) {
            const int part = n >> 10;
            const int e    = n & 1023;
            const int h    = e >> 6;
            const int d    = e & 63;
            const int b    = m >> 11;
            const int s    = m & 2047;
            float* dst = (part == 0) ? g_q : (part == 1) ? g_k : g_v;
            *reinterpret_cast<float4*>(
                &dst[(((size_t)(b * HEADS + h) * SEQ) + s) * HD + d]) = v;
        } else {
            *reinterpret_cast<float4*>(&C[(size_t)m * EMB + n]) = v;
        }
    }
}

// ---------------------------------------------------------------------------
// RoPE + split: reads g_q/g_k fp32, writes bf16 hi/lo (q pre-scaled by 1/8).
// ---------------------------------------------------------------------------
__global__ __launch_bounds__(256)
void rope_split()
{
    const int warp = (blockIdx.x * blockDim.x + threadIdx.x) >> 5;
    const int lane = threadIdx.x & 31;
    if (warp >= BATCH * HEADS * SEQ) return;
    const int s = warp & (SEQ - 1);

    const float* qp = g_q + (size_t)warp * HD;
    const float* kp = g_k + (size_t)warp * HD;

    const float inv_freq = powf(10000.0f, -(float)(2 * lane) / (float)HD);
    float c, sn;
    sincosf((float)s * inv_freq, &sn, &c);

    float q1 = qp[lane], q2 = qp[lane + 32];
    float k1 = kp[lane], k2 = kp[lane + 32];
    float qa = (q1 * c - q2 * sn) * 0.125f;
    float qb = (q2 * c + q1 * sn) * 0.125f;
    float ka = k1 * c - k2 * sn;
    float kb = k2 * c + k1 * sn;

    const size_t base = (size_t)warp * HD;
    __nv_bfloat16 h;
    h = __float2bfloat16_rn(qa); g_qh[base + lane] = h;
    g_ql[base + lane] = __float2bfloat16_rn(qa - __bfloat162float(h));
    h = __float2bfloat16_rn(qb); g_qh[base + lane + 32] = h;
    g_ql[base + lane + 32] = __float2bfloat16_rn(qb - __bfloat162float(h));
    h = __float2bfloat16_rn(ka); g_kh[base + lane] = h;
    g_kl[base + lane] = __float2bfloat16_rn(ka - __bfloat162float(h));
    h = __float2bfloat16_rn(kb); g_kh[base + lane + 32] = h;
    g_kl[base + lane + 32] = __float2bfloat16_rn(kb - __bfloat162float(h));
}

// ---------------------------------------------------------------------------
// V prep: transpose [B,H,S,hd] fp32 -> [B,H,hd,S] bf16 hi/lo
// ---------------------------------------------------------------------------
__global__ __launch_bounds__(256)
void vprep()
{
    __shared__ float vs[64][65];
    const int tid  = threadIdx.x;
    const int sb   = blockIdx.x * 64;
    const int head = blockIdx.y;
    const float* V = g_v + ((size_t)head * SEQ + sb) * HD;
#pragma unroll
    for (int i = 0; i < 16; i++) {
        const int e = tid + i * 256;
        vs[e >> 6][e & 63] = V[(size_t)(e >> 6) * HD + (e & 63)];
    }
    __syncthreads();
    const int d  = tid >> 2;
    const int s4 = (tid & 3) * 16;
    __nv_bfloat16 hb[16], lb[16];
#pragma unroll
    for (int j = 0; j < 16; j++) {
        const float f = vs[s4 + j][d];
        const __nv_bfloat16 h = __float2bfloat16_rn(f);
        hb[j] = h;
        lb[j] = __float2bfloat16_rn(f - __bfloat162float(h));
    }
    const size_t base = (size_t)head * HD * SEQ + (size_t)d * SEQ + sb + s4;
    reinterpret_cast<uint4*>(g_vth + base)[0] = reinterpret_cast<uint4*>(hb)[0];
    reinterpret_cast<uint4*>(g_vth + base)[1] = reinterpret_cast<uint4*>(hb)[1];
    reinterpret_cast<uint4*>(g_vtl + base)[0] = reinterpret_cast<uint4*>(lb)[0];
    reinterpret_cast<uint4*>(g_vtl + base)[1] = reinterpret_cast<uint4*>(lb)[1];
}

// ---------------------------------------------------------------------------
// Tensor-core flash attention. grid=(SEQ/128, B*H), 256 threads (8 warps).
// Warp w owns q rows [qb*128 + w*16, +16). 3-term split QK^T and P*V.
// smem: double-buffered {Kh, Kl, Vth, Vtl}, each 64 rows x 72-elem stride.
// ---------------------------------------------------------------------------
#define AK_STR   72
#define ATILE_EL (64 * AK_STR)
#define ABUF_EL  (4 * ATILE_EL)
#define AT_SMEM  (2 * ABUF_EL * 2)      // 73728 bytes

__device__ __forceinline__ void attn_stage(uint32_t sb, int buf, int kb,
                                           size_t hbase, size_t vbase, int tid)
{
#pragma unroll
    for (int i = 0; i < 8; i++) {
        const int t  = i >> 1;                       // tile 0..3
        const int r  = (tid >> 3) + 32 * (i & 1);    // 0..63
        const int ch = tid & 7;                      // 16B chunk
        const __nv_bfloat16* src;
        if (t == 0)      src = g_kh  + hbase + (size_t)(kb * 64 + r) * HD + ch * 8;
        else if (t == 1) src = g_kl  + hbase + (size_t)(kb * 64 + r) * HD + ch * 8;
        else if (t == 2) src = g_vth + vbase + (size_t)r * SEQ + kb * 64 + ch * 8;
        else             src = g_vtl + vbase + (size_t)r * SEQ + kb * 64 + ch * 8;
        cp_async16(sb + (buf * ABUF_EL + t * ATILE_EL + r * AK_STR + ch * 8) * 2, src);
    }
}

__global__ __launch_bounds__(256)
void attn_mma()
{
    extern __shared__ __align__(16) __nv_bfloat16 sk[];
    const uint32_t sb = smem_u32(sk);
    const int tid  = threadIdx.x;
    const int wid  = tid >> 5;
    const int lane = tid & 31;
    const int gid  = lane >> 2;      // 0..7
    const int tidg = lane & 3;       // 0..3
    const int qb   = blockIdx.x;
    const int head = blockIdx.y;     // b*HEADS + h

    const size_t hbase = (size_t)head * SEQ * HD;
    const size_t vbase = (size_t)head * HD * SEQ;

    // Q A-fragments (held in registers for whole CTA lifetime)
    uint32_t qah[4][4], qal[4][4];
    {
        const int r0 = qb * 128 + wid * 16 + gid;
        const uint32_t* q0h = reinterpret_cast<const uint32_t*>(g_qh + hbase + (size_t)r0 * HD);
        const uint32_t* q1h = reinterpret_cast<const uint32_t*>(g_qh + hbase + (size_t)(r0 + 8) * HD);
        const uint32_t* q0l = reinterpret_cast<const uint32_t*>(g_ql + hbase + (size_t)r0 * HD);
        const uint32_t* q1l = reinterpret_cast<const uint32_t*>(g_ql + hbase + (size_t)(r0 + 8) * HD);
#pragma unroll
        for (int ks = 0; ks < 4; ks++) {
            qah[ks][0] = q0h[ks * 8 + tidg];
            qah[ks][1] = q1h[ks * 8 + tidg];
            qah[ks][2] = q0h[ks * 8 + tidg + 4];
            qah[ks][3] = q1h[ks * 8 + tidg + 4];
            qal[ks][0] = q0l[ks * 8 + tidg];
            qal[ks][1] = q1l[ks * 8 + tidg];
            qal[ks][2] = q0l[ks * 8 + tidg + 4];
            qal[ks][3] = q1l[ks * 8 + tidg + 4];
        }
    }

    float o[8][4];
#pragma unroll
    for (int nt = 0; nt < 8; nt++)
#pragma unroll
        for (int j = 0; j < 4; j++) o[nt][j] = 0.0f;
    float m0 = -1e30f, m1 = -1e30f, l0 = 0.0f, l1 = 0.0f;

    attn_stage(sb, 0, 0, hbase, vbase, tid);
    cp_commit();

    const int NKB = SEQ / 64;    // 32
    for (int kb = 0; kb < NKB; kb++) {
        if (kb + 1 < NKB) {
            attn_stage(sb, (kb + 1) & 1, kb + 1, hbase, vbase, tid);
            cp_commit();
            cp_wait<1>();
        } else {
            cp_wait<0>();
        }
        __syncthreads();

        const __nv_bfloat16* bs = sk + (kb & 1) * ABUF_EL;
        const __nv_bfloat16* Kh = bs;
        const __nv_bfloat16* Kl = bs + ATILE_EL;
        const __nv_bfloat16* Vh = bs + 2 * ATILE_EL;
        const __nv_bfloat16* Vl = bs + 3 * ATILE_EL;

        // ---- S = (Q/8) K^T, 3-term split ----
        float s[8][4];
#pragma unroll
        for (int nt = 0; nt < 8; nt++)
#pragma unroll
            for (int j = 0; j < 4; j++) s[nt][j] = 0.0f;

#pragma unroll
        for (int ks = 0; ks < 4; ks++) {
#pragma unroll
            for (int nt = 0; nt < 8; nt++) {
                const uint32_t* krh = reinterpret_cast<const uint32_t*>(
                    Kh + (nt * 8 + gid) * AK_STR);
                const uint32_t* krl = reinterpret_cast<const uint32_t*>(
                    Kl + (nt * 8 + gid) * AK_STR);
                const uint32_t bh0 = krh[8 * ks + tidg];
                const uint32_t bh1 = krh[8 * ks + tidg + 4];
                const uint32_t bl0 = krl[8 * ks + tidg];
                const uint32_t bl1 = krl[8 * ks + tidg + 4];
                mma16816(s[nt], qah[ks], bh0, bh1);
                mma16816(s[nt], qah[ks], bl0, bl1);
                mma16816(s[nt], qal[ks], bh0, bh1);
            }
        }

        // ---- online softmax on register tiles ----
        float mx0 = -1e30f, mx1 = -1e30f;
#pragma unroll
        for (int nt = 0; nt < 8; nt++) {
            mx0 = fmaxf(mx0, fmaxf(s[nt][0], s[nt][1]));
            mx1 = fmaxf(mx1, fmaxf(s[nt][2], s[nt][3]));
        }
        mx0 = fmaxf(mx0, __shfl_xor_sync(0xffffffffu, mx0, 1));
        mx0 = fmaxf(mx0, __shfl_xor_sync(0xffffffffu, mx0, 2));
        mx1 = fmaxf(mx1, __shfl_xor_sync(0xffffffffu, mx1, 1));
        mx1 = fmaxf(mx1, __shfl_xor_sync(0xffffffffu, mx1, 2));
        const float mn0 = fmaxf(m0, mx0), mn1 = fmaxf(m1, mx1);
        const float c0 = __expf(m0 - mn0), c1 = __expf(m1 - mn1);
        float rs0 = 0.0f, rs1 = 0.0f;
#pragma unroll
        for (int nt = 0; nt < 8; nt++) {
            s[nt][0] = __expf(s[nt][0] - mn0);
            s[nt][1] = __expf(s[nt][1] - mn0);
            s[nt][2] = __expf(s[nt][2] - mn1);
            s[nt][3] = __expf(s[nt][3] - mn1);
            rs0 += s[nt][0] + s[nt][1];
            rs1 += s[nt][2] + s[nt][3];
        }
        rs0 += __shfl_xor_sync(0xffffffffu, rs0, 1);
        rs0 += __shfl_xor_sync(0xffffffffu, rs0, 2);
        rs1 += __shfl_xor_sync(0xffffffffu, rs1, 1);
        rs1 += __shfl_xor_sync(0xffffffffu, rs1, 2);
        l0 = l0 * c0 + rs0;  l1 = l1 * c1 + rs1;
        m0 = mn0;  m1 = mn1;
#pragma unroll
        for (int nt = 0; nt < 8; nt++) {
            o[nt][0] *= c0; o[nt][1] *= c0;
            o[nt][2] *= c1; o[nt][3] *= c1;
        }

        // ---- O += P V, 3-term split; P converts C-layout -> A-layout in regs ----
#pragma unroll
        for (int ks = 0; ks < 4; ks++) {
            uint32_t pah[4], pal[4];
            pah[0] = pack_bf16x2(s[2 * ks][0], s[2 * ks][1]);
            pah[1] = pack_bf16x2(s[2 * ks][2], s[2 * ks][3]);
            pah[2] = pack_bf16x2(s[2 * ks + 1][0], s[2 * ks + 1][1]);
            pah[3] = pack_bf16x2(s[2 * ks + 1][2], s[2 * ks + 1][3]);
            pal[0] = pack_bf16x2(bres(s[2 * ks][0]), bres(s[2 * ks][1]));
            pal[1] = pack_bf16x2(bres(s[2 * ks][2]), bres(s[2 * ks][3]));
            pal[2] = pack_bf16x2(bres(s[2 * ks + 1][0]), bres(s[2 * ks + 1][1]));
            pal[3] = pack_bf16x2(bres(s[2 * ks + 1][2]), bres(s[2 * ks + 1][3]));
#pragma unroll
            for (int nt = 0; nt < 8; nt++) {
                const uint32_t* vrh = reinterpret_cast<const uint32_t*>(
                    Vh + (nt * 8 + gid) * AK_STR);
                const uint32_t* vrl = reinterpret_cast<const uint32_t*>(
                    Vl + (nt * 8 + gid) * AK_STR);
                const uint32_t bh0 = vrh[8 * ks + tidg];
                const uint32_t bh1 = vrh[8 * ks + tidg + 4];
                const uint32_t bl0 = vrl[8 * ks + tidg];
                const uint32_t bl1 = vrl[8 * ks + tidg + 4];
                mma16816(o[nt], pah, bh0, bh1);
                mma16816(o[nt], pah, bl0, bl1);
                mma16816(o[nt], pal, bh0, bh1);
            }
        }
        __syncthreads();
    }

    // ---- epilogue: normalize, split to bf16 hi/lo, write [B*S, E] ----
    const float i0 = 1.0f / l0, i1 = 1.0f / l1;
    const int b = head >> 4, h = head & 15;
    const int s0 = qb * 128 + wid * 16;
#pragma unroll
    for (int nt = 0; nt < 8; nt++) {
        const float f0 = o[nt][0] * i0, f1 = o[nt][1] * i0;
        const float f2 = o[nt][2] * i1, f3 = o[nt][3] * i1;
        const size_t base0 = (size_t)(b * SEQ + s0 + gid) * EMB +
                             h * 64 + nt * 8 + 2 * tidg;
        const size_t base1 = (size_t)(b * SEQ + s0 + gid + 8) * EMB +
                             h * 64 + nt * 8 + 2 * tidg;
        *reinterpret_cast<uint32_t*>(g_aoh + base0) = pack_bf16x2(f0, f1);
        *reinterpret_cast<uint32_t*>(g_aol + base0) = pack_bf16x2(bres(f0), bres(f1));
        *reinterpret_cast<uint32_t*>(g_aoh + base1) = pack_bf16x2(f2, f3);
        *reinterpret_cast<uint32_t*>(g_aol + base1) = pack_bf16x2(bres(f2), bres(f3));
    }
}

// ---------------------------------------------------------------------------
extern "C" void kernel_launch(void* const* d_in, const int* in_sizes, int n_in,
                              void* d_out, int out_size)
{
    const float* hidden = (const float*)d_in[0];
    const float* qkv_w  = (const float*)d_in[1];
    const float* qkv_b  = (const float*)d_in[2];
    const float* proj_w = (const float*)d_in[3];
    const float* proj_b = (const float*)d_in[4];
    float* out = (float*)d_out;

    // 0) split fp32 -> bf16 hi/lo
    split_kernel<0><<<(MROWS * EMB / 4 + 255) / 256, 256>>>(hidden, MROWS * EMB / 4);
    split_kernel<1><<<(QKVN * EMB / 4 + 255) / 256, 256>>>(qkv_w, QKVN * EMB / 4);
    split_kernel<2><<<(EMB * EMB / 4 + 255) / 256, 256>>>(proj_w, EMB * EMB / 4);

    // 1) QKV GEMM (WMMA split bf16) + scatter to q/k/v fp32
    cudaFuncSetAttribute(gemm_wmma<1>,
                         cudaFuncAttributeMaxDynamicSharedMemorySize, GSMEM);
    gemm_wmma<1><<<dim3(QKVN / 128, MROWS / 128), 256, GSMEM>>>(qkv_b, nullptr);

    // 2) RoPE + bf16 split of q,k ; transpose+split of v
    rope_split<<<(BATCH * HEADS * SEQ + 7) / 8, 256>>>();
    vprep<<<dim3(SEQ / 64, BATCH * HEADS), 256>>>();

    // 3) tensor-core flash attention (split bf16), writes split output
    cudaFuncSetAttribute(attn_mma,
                         cudaFuncAttributeMaxDynamicSharedMemorySize, AT_SMEM);
    attn_mma<<<dim3(SEQ / 128, BATCH * HEADS), 256, AT_SMEM>>>();

    // 4) output projection (WMMA split bf16)
    cudaFuncSetAttribute(gemm_wmma<2>,
                         cudaFuncAttributeMaxDynamicSharedMemorySize, GSMEM);
    gemm_wmma<2><<<dim3(EMB / 128, MROWS / 128), 256, GSMEM>>>(proj_b, out);
}